// round 4
// baseline (speedup 1.0000x reference)
#include <cuda_runtime.h>
#include <cstdint>

#define D      512
#define BATCH  256
#define TOPK   2
#define NEXP   16
#define NPAIR  (BATCH * TOPK)
#define MAXCH  48          // worst-case sum ceil(M_e/16) over 16 experts
#define XS_STRIDE 20       // 16 data + 4 pad floats; 80B => 16B-aligned rows

// ---------------- scratch ----------------
__device__ float g_iv[NPAIR * D];
__device__ float g_ov[NPAIR * D];
__device__ float g_dv[NPAIR * D];
__device__ float g_bv[NPAIR * D];

// ---------------- packed f32x2 helpers ----------------
__device__ __forceinline__ uint64_t dupf2(float w) {
    uint64_t r;
    asm("mov.b64 %0, {%1, %1};" : "=l"(r) : "r"(__float_as_uint(w)));
    return r;
}
__device__ __forceinline__ void fma2(uint64_t& acc, uint64_t a, uint64_t b) {
    asm("fma.rn.f32x2 %0, %1, %2, %0;" : "+l"(acc) : "l"(a), "l"(b));
}

// ---------------- kernel 1: grouped GEMM with in-block counting sort ----------------
// grid = (4 col-tiles of 128, MAXCH chunks, 4 banks), block = 128 threads.
// Warp 0 rebuilds the (deterministic) expert-sorted pair list + chunk table in
// smem (~0.5us), so no separate sort launch. Thread owns 1 column and 16 row
// accumulators as 8 packed f32x2. Inner loop unrolled x16 for LDG latency cover.
__global__ __launch_bounds__(128) void gemm_kernel(
    const float* __restrict__ x,
    const float* __restrict__ iw, const float* __restrict__ ow,
    const float* __restrict__ dw, const float* __restrict__ bb,
    const int* __restrict__ widx, const int* __restrict__ bidx) {

    __shared__ __align__(16) float xs[D * XS_STRIDE];   // 40KB
    __shared__ int slist[NPAIR];
    __shared__ int schunk[MAXCH];
    __shared__ int scnt[NEXP], soff[NEXP + 1];
    __shared__ int snch;

    int bank = blockIdx.z;
    bool isW = bank < 3;
    const int* idx = isW ? widx : bidx;

    int t = threadIdx.x;

    // ---- in-block deterministic counting sort (warp 0) ----
    if (t < 32) {
        if (t < NEXP) scnt[t] = 0;
        __syncwarp();
        // pass 1: histogram (ballot-leader adds; deterministic)
        int e_r[16];
#pragma unroll
        for (int r = 0; r < 16; r++) {
            int e = idx[r * 32 + t];
            e_r[r] = e;
            unsigned mask = __match_any_sync(0xffffffffu, e);
            if ((__ffs(mask) - 1) == t) scnt[e] += __popc(mask);
            __syncwarp();
        }
        if (t == 0) {
            int s = 0;
            int n = 0;
#pragma unroll
            for (int e = 0; e < NEXP; e++) {
                soff[e] = s;
                int c = scnt[e];
                for (int q = 0; q < c; q += 16) {
                    int rows = min(16, c - q);
                    schunk[n++] = (s + q) | (e << 16) | (rows << 24);
                }
                s += c;
            }
            soff[NEXP] = s;
            snch = n;
        }
        __syncwarp();
        if (t < NEXP) scnt[t] = soff[t];   // running positions
        __syncwarp();
        // pass 2: stable scatter via match_any rank
#pragma unroll
        for (int r = 0; r < 16; r++) {
            int e = e_r[r];
            unsigned mask = __match_any_sync(0xffffffffu, e);
            int rank = scnt[e] + __popc(mask & ((1u << t) - 1u));
            __syncwarp();
            if ((__ffs(mask) - 1) == t) scnt[e] += __popc(mask);
            slist[rank] = r * 32 + t;
            __syncwarp();
        }
    }
    __syncthreads();

    if ((int)blockIdx.y >= snch) return;

    int packed = schunk[blockIdx.y];
    int s    = packed & 0xFFFF;
    int e    = (packed >> 16) & 0xFF;
    int rows = (packed >> 24) & 0xFF;

    const float* W  = ((bank == 0) ? iw : (bank == 1) ? ow : (bank == 2) ? dw : bb)
                      + (size_t)e * D * D;
    float* out = (bank == 0) ? g_iv : (bank == 1) ? g_ov : (bank == 2) ? g_dv : g_bv;

    int col = blockIdx.x * 128 + t;

    // fill transposed x chunk (coalesced LDG; zero-pad rows >= rows)
    for (int idx2 = t; idx2 < 16 * D; idx2 += 128) {
        int m  = idx2 >> 9;
        int kk = idx2 & (D - 1);
        float val = 0.0f;
        if (m < rows) val = x[(slist[s + m] >> 1) * D + kk];
        xs[kk * XS_STRIDE + m] = val;
    }
    __syncthreads();

    uint64_t acc[8];
#pragma unroll
    for (int j = 0; j < 8; j++) acc[j] = 0ull;

    const float* Wc = W + col;
#pragma unroll 16
    for (int kk = 0; kk < D; kk++) {
        float w = Wc[kk * D];
        uint64_t ww = dupf2(w);
        const ulonglong2* row = (const ulonglong2*)&xs[kk * XS_STRIDE];
        ulonglong2 r0 = row[0];
        ulonglong2 r1 = row[1];
        ulonglong2 r2 = row[2];
        ulonglong2 r3 = row[3];
        fma2(acc[0], r0.x, ww);
        fma2(acc[1], r0.y, ww);
        fma2(acc[2], r1.x, ww);
        fma2(acc[3], r1.y, ww);
        fma2(acc[4], r2.x, ww);
        fma2(acc[5], r2.y, ww);
        fma2(acc[6], r3.x, ww);
        fma2(acc[7], r3.y, ww);
    }

#pragma unroll
    for (int j = 0; j < 8; j++) {
        float2 f2 = *reinterpret_cast<float2*>(&acc[j]);
        int r = 2 * j;
        if (r < rows)     out[(size_t)slist[s + r] * D + col]     = f2.x;
        if (r + 1 < rows) out[(size_t)slist[s + r + 1] * D + col] = f2.y;
    }
}

// ---------------- kernel 2: rank-2 mix + analytic LayerNorm + bmix ----------------
// Wmix[b,i,o] = p_i*u_o + q_i*v_o + delta_{io}*g_i. Row mean/var closed-form.
// Per-row params folded to (p*rstd, q*rstd, -mean*rstd, g*rstd); inner body is
// 1 LDS.128 + 8 FFMA + STG.128(streaming, evict-first).
__global__ __launch_bounds__(128) void mix_ln_kernel(
    const float* __restrict__ wp, const float* __restrict__ bp,
    float* __restrict__ outp) {

    int b  = blockIdx.y;
    int r0 = blockIdx.x * 128;
    int t  = threadIdx.x;

    __shared__ float u[D], v[D];
    __shared__ __align__(16) float4 sparams[128];   // {pr, qr, c, gr}
    __shared__ float red[4][5];

    const float* u_g = g_ov + (size_t)(2 * b) * D;
    const float* v_g = g_ov + (size_t)(2 * b + 1) * D;
    float4 u4 = ((const float4*)u_g)[t];
    float4 v4 = ((const float4*)v_g)[t];
    ((float4*)u)[t] = u4;
    ((float4*)v)[t] = v4;

    float lu  = u4.x + u4.y + u4.z + u4.w;
    float lv  = v4.x + v4.y + v4.z + v4.w;
    float luu = u4.x * u4.x + u4.y * u4.y + u4.z * u4.z + u4.w * u4.w;
    float lvv = v4.x * v4.x + v4.y * v4.y + v4.z * v4.z + v4.w * v4.w;
    float luv = u4.x * v4.x + u4.y * v4.y + u4.z * v4.z + u4.w * v4.w;
#pragma unroll
    for (int sft = 16; sft > 0; sft >>= 1) {
        lu  += __shfl_xor_sync(0xffffffffu, lu, sft);
        lv  += __shfl_xor_sync(0xffffffffu, lv, sft);
        luu += __shfl_xor_sync(0xffffffffu, luu, sft);
        lvv += __shfl_xor_sync(0xffffffffu, lvv, sft);
        luv += __shfl_xor_sync(0xffffffffu, luv, sft);
    }
    int lane = t & 31, wrp = t >> 5;
    if (lane == 0) {
        red[wrp][0] = lu; red[wrp][1] = lv; red[wrp][2] = luu;
        red[wrp][3] = lvv; red[wrp][4] = luv;
    }
    __syncthreads();
    float Su  = red[0][0] + red[1][0] + red[2][0] + red[3][0];
    float Sv  = red[0][1] + red[1][1] + red[2][1] + red[3][1];
    float Suu = red[0][2] + red[1][2] + red[2][2] + red[3][2];
    float Svv = red[0][3] + red[1][3] + red[2][3] + red[3][3];
    float Suv = red[0][4] + red[1][4] + red[2][4] + red[3][4];

    {
        int i = r0 + t;
        float wp0 = wp[2 * b], wp1 = wp[2 * b + 1];
        float p = wp0 * g_iv[(size_t)(2 * b) * D + i];
        float q = wp1 * g_iv[(size_t)(2 * b + 1) * D + i];
        float g = wp0 * g_dv[(size_t)(2 * b) * D + i]
                + wp1 * g_dv[(size_t)(2 * b + 1) * D + i];
        const float invD = 1.0f / (float)D;
        float mean = (p * Su + q * Sv + g) * invD;
        float ex2  = (p * p * Suu + 2.0f * p * q * Suv + q * q * Svv
                      + 2.0f * g * (p * u[i] + q * v[i]) + g * g) * invD;
        float var  = ex2 - mean * mean;
        float rstd = rsqrtf(var + 1e-5f);
        float4 pr;
        pr.x = p * rstd;
        pr.y = q * rstd;
        pr.z = -mean * rstd;
        pr.w = g * rstd;
        sparams[t] = pr;
    }
    __syncthreads();

    float* orow = outp + ((size_t)b * D + r0) * D + (t << 2);

    if (wrp == blockIdx.x) {
        int base = t << 2;
#pragma unroll 4
        for (int r = 0; r < 128; r++) {
            float4 P = sparams[r];
            float4 o;
            o.x = fmaf(P.y, v4.x, fmaf(P.x, u4.x, P.z));
            o.y = fmaf(P.y, v4.y, fmaf(P.x, u4.y, P.z));
            o.z = fmaf(P.y, v4.z, fmaf(P.x, u4.z, P.z));
            o.w = fmaf(P.y, v4.w, fmaf(P.x, u4.w, P.z));
            int dj = (r0 + r) - base;
            if (dj == 0) o.x += P.w;
            if (dj == 1) o.y += P.w;
            if (dj == 2) o.z += P.w;
            if (dj == 3) o.w += P.w;
            __stcs((float4*)(orow + (size_t)r * D), o);
        }
    } else {
#pragma unroll 4
        for (int r = 0; r < 128; r++) {
            float4 P = sparams[r];
            float4 o;
            o.x = fmaf(P.y, v4.x, fmaf(P.x, u4.x, P.z));
            o.y = fmaf(P.y, v4.y, fmaf(P.x, u4.y, P.z));
            o.z = fmaf(P.y, v4.z, fmaf(P.x, u4.z, P.z));
            o.w = fmaf(P.y, v4.w, fmaf(P.x, u4.w, P.z));
            __stcs((float4*)(orow + (size_t)r * D), o);
        }
    }

    // bmix (row-tile 0 only): bmix[b,:] = bp0*bv0 + bp1*bv1
    if (blockIdx.x == 0) {
        float bp0 = bp[2 * b], bp1 = bp[2 * b + 1];
        float4 b0 = ((const float4*)(g_bv + (size_t)(2 * b) * D))[t];
        float4 b1 = ((const float4*)(g_bv + (size_t)(2 * b + 1) * D))[t];
        float4 o;
        o.x = bp0 * b0.x + bp1 * b1.x;
        o.y = bp0 * b0.y + bp1 * b1.y;
        o.z = bp0 * b0.z + bp1 * b1.z;
        o.w = bp0 * b0.w + bp1 * b1.w;
        __stcs((float4*)(outp + (size_t)BATCH * D * D + (size_t)b * D) + t, o);
    }
}

// ---------------- launch ----------------
extern "C" void kernel_launch(void* const* d_in, const int* in_sizes, int n_in,
                              void* d_out, int out_size) {
    const float* x    = (const float*)d_in[0];
    const float* wp   = (const float*)d_in[1];
    const float* bpr  = (const float*)d_in[2];
    const float* iw   = (const float*)d_in[3];
    const float* ow   = (const float*)d_in[4];
    const float* dw   = (const float*)d_in[5];
    const float* bb   = (const float*)d_in[6];
    const int*   widx = (const int*)d_in[7];
    const int*   bidx = (const int*)d_in[8];
    float* outp = (float*)d_out;

    gemm_kernel<<<dim3(4, MAXCH, 4), 128>>>(x, iw, ow, dw, bb, widx, bidx);
    mix_ln_kernel<<<dim3(4, BATCH), 128>>>(wp, bpr, outp);
}

// round 5
// speedup vs baseline: 1.5731x; 1.5731x over previous
#include <cuda_runtime.h>
#include <cstdint>

#define D      512
#define BATCH  256
#define TOPK   2
#define NEXP   16
#define NPAIR  (BATCH * TOPK)
#define MAXCH  48          // worst-case sum ceil(M_e/16) over 16 experts = 48
#define XS_STRIDE 20       // 16 data + 4 pad floats; 80B => 16B-aligned rows

// ---------------- scratch ----------------
__device__ float g_iv[NPAIR * D];
__device__ float g_ov[NPAIR * D];
__device__ float g_dv[NPAIR * D];
__device__ float g_bv[NPAIR * D];
__device__ int   g_list_w[NPAIR];
__device__ int   g_list_b[NPAIR];
__device__ int   g_chunks_w[MAXCH];   // packed: start | e<<16 | rows<<24
__device__ int   g_chunks_b[MAXCH];
__device__ int   g_nch_w, g_nch_b;

// ---------------- kernel 0: counting sort + chunk work-list ----------------
__global__ void sort_kernel(const int* __restrict__ widx, const int* __restrict__ bidx) {
    __shared__ int cw[NEXP], cb[NEXP], offw[NEXP + 1], offb[NEXP + 1], pw[NEXP], pb[NEXP];
    int t = threadIdx.x;                       // 512 threads == pair id
    if (t < NEXP) { cw[t] = 0; cb[t] = 0; }
    __syncthreads();
    int ew = widx[t];
    int eb = bidx[t];
    atomicAdd(&cw[ew], 1);
    atomicAdd(&cb[eb], 1);
    __syncthreads();
    if (t == 0) {
        int s = 0;
        for (int e = 0; e < NEXP; e++) { offw[e] = s; s += cw[e]; }
        offw[NEXP] = s;
        int n = 0;
        for (int e = 0; e < NEXP; e++)
            for (int c = offw[e]; c < offw[e + 1]; c += 16) {
                int rows = min(16, offw[e + 1] - c);
                g_chunks_w[n++] = c | (e << 16) | (rows << 24);
            }
        g_nch_w = n;
    }
    if (t == 32) {
        int s = 0;
        for (int e = 0; e < NEXP; e++) { offb[e] = s; s += cb[e]; }
        offb[NEXP] = s;
        int n = 0;
        for (int e = 0; e < NEXP; e++)
            for (int c = offb[e]; c < offb[e + 1]; c += 16) {
                int rows = min(16, offb[e + 1] - c);
                g_chunks_b[n++] = c | (e << 16) | (rows << 24);
            }
        g_nch_b = n;
    }
    __syncthreads();
    if (t < NEXP) { pw[t] = offw[t]; pb[t] = offb[t]; }
    __syncthreads();
    int posw = atomicAdd(&pw[ew], 1);
    g_list_w[posw] = t;
    int posb = atomicAdd(&pb[eb], 1);
    g_list_b[posb] = t;
}

// ---------------- packed f32x2 helpers ----------------
__device__ __forceinline__ uint64_t dupf2(float w) {
    uint64_t r;
    asm("mov.b64 %0, {%1, %1};" : "=l"(r) : "r"(__float_as_uint(w)));
    return r;
}
__device__ __forceinline__ void fma2(uint64_t& acc, uint64_t a, uint64_t b) {
    asm("fma.rn.f32x2 %0, %1, %2, %0;" : "+l"(acc) : "l"(a), "l"(b));
}

// ---------------- kernel 1: balanced grouped GEMM (FFMA2, unroll 16) ----------------
// grid = (4 col-tiles of 128, MAXCH chunks, 4 banks), block = 128 threads.
// Thread owns 1 column, 16 row-accumulators held as 8 packed f32x2 regs.
// Per kk: 1 LDG (W) + 4 LDS.128 (broadcast) + 1 pack + 8 FFMA2; unroll 16 so
// ptxas front-batches ~16 W loads per warp iteration (covers L2/DRAM latency).
__global__ __launch_bounds__(128) void gemm_kernel(
    const float* __restrict__ x,
    const float* __restrict__ iw, const float* __restrict__ ow,
    const float* __restrict__ dw, const float* __restrict__ bb) {

    int bank = blockIdx.z;
    bool isW = bank < 3;
    int nch = isW ? g_nch_w : g_nch_b;
    if ((int)blockIdx.y >= nch) return;

    __shared__ __align__(16) float xs[D * XS_STRIDE];   // 40KB

    int packed = (isW ? g_chunks_w : g_chunks_b)[blockIdx.y];
    int s    = packed & 0xFFFF;
    int e    = (packed >> 16) & 0xFF;
    int rows = (packed >> 24) & 0xFF;

    const int* list = isW ? g_list_w : g_list_b;
    const float* W  = ((bank == 0) ? iw : (bank == 1) ? ow : (bank == 2) ? dw : bb)
                      + (size_t)e * D * D;
    float* out = (bank == 0) ? g_iv : (bank == 1) ? g_ov : (bank == 2) ? g_dv : g_bv;

    int t   = threadIdx.x;
    int col = blockIdx.x * 128 + t;

    // fill transposed x chunk (coalesced LDG; zero-pad rows >= rows)
    for (int idx2 = t; idx2 < 16 * D; idx2 += 128) {
        int m  = idx2 >> 9;
        int kk = idx2 & (D - 1);
        float val = 0.0f;
        if (m < rows) val = x[(list[s + m] >> 1) * D + kk];
        xs[kk * XS_STRIDE + m] = val;
    }
    __syncthreads();

    uint64_t acc[8];
#pragma unroll
    for (int j = 0; j < 8; j++) acc[j] = 0ull;

    const float* Wc = W + col;
#pragma unroll 16
    for (int kk = 0; kk < D; kk++) {
        float w = Wc[kk * D];
        uint64_t ww = dupf2(w);
        const ulonglong2* row = (const ulonglong2*)&xs[kk * XS_STRIDE];
        ulonglong2 r0 = row[0];
        ulonglong2 r1 = row[1];
        ulonglong2 r2 = row[2];
        ulonglong2 r3 = row[3];
        fma2(acc[0], r0.x, ww);
        fma2(acc[1], r0.y, ww);
        fma2(acc[2], r1.x, ww);
        fma2(acc[3], r1.y, ww);
        fma2(acc[4], r2.x, ww);
        fma2(acc[5], r2.y, ww);
        fma2(acc[6], r3.x, ww);
        fma2(acc[7], r3.y, ww);
    }

#pragma unroll
    for (int j = 0; j < 8; j++) {
        float2 f2 = *reinterpret_cast<float2*>(&acc[j]);
        int r = 2 * j;
        if (r < rows)     out[(size_t)list[s + r] * D + col]     = f2.x;
        if (r + 1 < rows) out[(size_t)list[s + r + 1] * D + col] = f2.y;
    }
}

// ---------------- kernel 2: rank-2 mix + analytic LayerNorm + bmix ----------------
// Wmix[b,i,o] = p_i*u_o + q_i*v_o + delta_{io}*g_i. Row mean/var closed-form from
// Su,Sv,Suu,Svv,Suv. Per-row params folded to (p*rstd, q*rstd, -mean*rstd, g*rstd)
// so inner body = 1 LDS.128 + 8 FFMA + STG.128. Near the HBM write floor.
__global__ __launch_bounds__(128) void mix_ln_kernel(
    const float* __restrict__ wp, const float* __restrict__ bp,
    float* __restrict__ outp) {

    int b  = blockIdx.y;
    int r0 = blockIdx.x * 128;
    int t  = threadIdx.x;

    __shared__ float u[D], v[D];
    __shared__ __align__(16) float4 sparams[128];   // {pr, qr, c, gr}
    __shared__ float red[4][5];

    const float* u_g = g_ov + (size_t)(2 * b) * D;
    const float* v_g = g_ov + (size_t)(2 * b + 1) * D;
    float4 u4 = ((const float4*)u_g)[t];
    float4 v4 = ((const float4*)v_g)[t];
    ((float4*)u)[t] = u4;
    ((float4*)v)[t] = v4;

    float lu  = u4.x + u4.y + u4.z + u4.w;
    float lv  = v4.x + v4.y + v4.z + v4.w;
    float luu = u4.x * u4.x + u4.y * u4.y + u4.z * u4.z + u4.w * u4.w;
    float lvv = v4.x * v4.x + v4.y * v4.y + v4.z * v4.z + v4.w * v4.w;
    float luv = u4.x * v4.x + u4.y * v4.y + u4.z * v4.z + u4.w * v4.w;
#pragma unroll
    for (int sft = 16; sft > 0; sft >>= 1) {
        lu  += __shfl_xor_sync(0xffffffffu, lu, sft);
        lv  += __shfl_xor_sync(0xffffffffu, lv, sft);
        luu += __shfl_xor_sync(0xffffffffu, luu, sft);
        lvv += __shfl_xor_sync(0xffffffffu, lvv, sft);
        luv += __shfl_xor_sync(0xffffffffu, luv, sft);
    }
    int lane = t & 31, wrp = t >> 5;
    if (lane == 0) {
        red[wrp][0] = lu; red[wrp][1] = lv; red[wrp][2] = luu;
        red[wrp][3] = lvv; red[wrp][4] = luv;
    }
    __syncthreads();
    float Su  = red[0][0] + red[1][0] + red[2][0] + red[3][0];
    float Sv  = red[0][1] + red[1][1] + red[2][1] + red[3][1];
    float Suu = red[0][2] + red[1][2] + red[2][2] + red[3][2];
    float Svv = red[0][3] + red[1][3] + red[2][3] + red[3][3];
    float Suv = red[0][4] + red[1][4] + red[2][4] + red[3][4];

    {
        int i = r0 + t;
        float wp0 = wp[2 * b], wp1 = wp[2 * b + 1];
        float p = wp0 * g_iv[(size_t)(2 * b) * D + i];
        float q = wp1 * g_iv[(size_t)(2 * b + 1) * D + i];
        float g = wp0 * g_dv[(size_t)(2 * b) * D + i]
                + wp1 * g_dv[(size_t)(2 * b + 1) * D + i];
        const float invD = 1.0f / (float)D;
        float mean = (p * Su + q * Sv + g) * invD;
        float ex2  = (p * p * Suu + 2.0f * p * q * Suv + q * q * Svv
                      + 2.0f * g * (p * u[i] + q * v[i]) + g * g) * invD;
        float var  = ex2 - mean * mean;
        float rstd = rsqrtf(var + 1e-5f);
        float4 pr;
        pr.x = p * rstd;
        pr.y = q * rstd;
        pr.z = -mean * rstd;
        pr.w = g * rstd;
        sparams[t] = pr;
    }
    __syncthreads();

    float* orow = outp + ((size_t)b * D + r0) * D + (t << 2);

    if (wrp == blockIdx.x) {
        int base = t << 2;
#pragma unroll 4
        for (int r = 0; r < 128; r++) {
            float4 P = sparams[r];
            float4 o;
            o.x = fmaf(P.y, v4.x, fmaf(P.x, u4.x, P.z));
            o.y = fmaf(P.y, v4.y, fmaf(P.x, u4.y, P.z));
            o.z = fmaf(P.y, v4.z, fmaf(P.x, u4.z, P.z));
            o.w = fmaf(P.y, v4.w, fmaf(P.x, u4.w, P.z));
            int dj = (r0 + r) - base;
            if (dj == 0) o.x += P.w;
            if (dj == 1) o.y += P.w;
            if (dj == 2) o.z += P.w;
            if (dj == 3) o.w += P.w;
            *(float4*)(orow + (size_t)r * D) = o;
        }
    } else {
#pragma unroll 4
        for (int r = 0; r < 128; r++) {
            float4 P = sparams[r];
            float4 o;
            o.x = fmaf(P.y, v4.x, fmaf(P.x, u4.x, P.z));
            o.y = fmaf(P.y, v4.y, fmaf(P.x, u4.y, P.z));
            o.z = fmaf(P.y, v4.z, fmaf(P.x, u4.z, P.z));
            o.w = fmaf(P.y, v4.w, fmaf(P.x, u4.w, P.z));
            *(float4*)(orow + (size_t)r * D) = o;
        }
    }

    // bmix (row-tile 0 only): bmix[b,:] = bp0*bv0 + bp1*bv1
    if (blockIdx.x == 0) {
        float bp0 = bp[2 * b], bp1 = bp[2 * b + 1];
        float4 b0 = ((const float4*)(g_bv + (size_t)(2 * b) * D))[t];
        float4 b1 = ((const float4*)(g_bv + (size_t)(2 * b + 1) * D))[t];
        float4 o;
        o.x = bp0 * b0.x + bp1 * b1.x;
        o.y = bp0 * b0.y + bp1 * b1.y;
        o.z = bp0 * b0.z + bp1 * b1.z;
        o.w = bp0 * b0.w + bp1 * b1.w;
        ((float4*)(outp + (size_t)BATCH * D * D + (size_t)b * D))[t] = o;
    }
}

// ---------------- launch ----------------
extern "C" void kernel_launch(void* const* d_in, const int* in_sizes, int n_in,
                              void* d_out, int out_size) {
    const float* x    = (const float*)d_in[0];
    const float* wp   = (const float*)d_in[1];
    const float* bpr  = (const float*)d_in[2];
    const float* iw   = (const float*)d_in[3];
    const float* ow   = (const float*)d_in[4];
    const float* dw   = (const float*)d_in[5];
    const float* bb   = (const float*)d_in[6];
    const int*   widx = (const int*)d_in[7];
    const int*   bidx = (const int*)d_in[8];
    float* outp = (float*)d_out;

    sort_kernel<<<1, NPAIR>>>(widx, bidx);
    gemm_kernel<<<dim3(4, MAXCH, 4), 128>>>(x, iw, ow, dw, bb);
    mix_ln_kernel<<<dim3(4, BATCH), 128>>>(wp, bpr, outp);
}